// round 17
// baseline (speedup 1.0000x reference)
#include <cuda_runtime.h>
#include <cuda_fp16.h>
#include <math.h>
#include <stdint.h>

#define B 2
#define S 2048
#define D 2048
#define H 16
#define KVH 4
#define HD 128
#define GROUPS (H/KVH)
#define SCALE 0.08838834764831845f
#define M_ROWS (B*S)          // 4096
#define NQKV (H*HD + 2*KVH*HD)   // 3072

// ---------------- scratch (__device__ globals; no allocation) --------------
__device__ float g_QKV[M_ROWS*NQKV];           // fused projection output (fp32)

__device__ __half g_x16[M_ROWS*D];
__device__ __half g_Wqkv16T[NQKV*D];           // [3072, 2048] fp16
__device__ __half g_Wo16T[D*H*HD];             // [2048, 2048] fp16
__device__ __half g_O16[M_ROWS*D];             // flash output, fp16

__device__ __half g_Q16[B*S*H*HD];
__device__ __half g_K16[B*S*KVH*HD];
__device__ __half g_V16[B*S*KVH*HD];

// ---------------------------- helpers --------------------------------------
__device__ __forceinline__ uint32_t smem_u32(const void* p) {
    uint32_t a;
    asm("{ .reg .u64 t; cvta.to.shared.u64 t, %1; cvt.u32.u64 %0, t; }"
        : "=r"(a) : "l"(p));
    return a;
}
__device__ __forceinline__ void cp16(uint32_t s, const void* g) {
    asm volatile("cp.async.cg.shared.global [%0], [%1], 16;" :: "r"(s), "l"(g));
}
#define CP_COMMIT() asm volatile("cp.async.commit_group;" ::: "memory")
#define CP_WAIT(n)  asm volatile("cp.async.wait_group %0;" :: "n"(n) : "memory")

__device__ __forceinline__ void mma16816h(float* c, const uint32_t* a,
                                          const uint32_t* b) {
    asm volatile(
        "mma.sync.aligned.m16n8k16.row.col.f32.f16.f16.f32 "
        "{%0,%1,%2,%3}, {%4,%5,%6,%7}, {%8,%9}, {%0,%1,%2,%3};"
        : "+f"(c[0]), "+f"(c[1]), "+f"(c[2]), "+f"(c[3])
        : "r"(a[0]), "r"(a[1]), "r"(a[2]), "r"(a[3]), "r"(b[0]), "r"(b[1]));
}
__device__ __forceinline__ void ldmx4(uint32_t* r, uint32_t addr) {
    asm volatile("ldmatrix.sync.aligned.m8n8.x4.shared.b16 {%0,%1,%2,%3}, [%4];"
        : "=r"(r[0]), "=r"(r[1]), "=r"(r[2]), "=r"(r[3]) : "r"(addr));
}
__device__ __forceinline__ void ldmx4t(uint32_t* r, uint32_t addr) {
    asm volatile("ldmatrix.sync.aligned.m8n8.x4.trans.shared.b16 "
                 "{%0,%1,%2,%3}, [%4];"
        : "=r"(r[0]), "=r"(r[1]), "=r"(r[2]), "=r"(r[3]) : "r"(addr));
}

// ---------------------------------------------------------------------------
// convert: fp32 packed -> fp16 packed
// ---------------------------------------------------------------------------
__global__ void convert_kernel(const float* __restrict__ X,
                               __half* __restrict__ out, int n4)
{
    int i = blockIdx.x * blockDim.x + threadIdx.x;
    if (i >= n4) return;
    float4 x = reinterpret_cast<const float4*>(X)[i];
    *reinterpret_cast<__half2*>(out + 4*(size_t)i) = __floats2half2_rn(x.x, x.y);
    *reinterpret_cast<__half2*>(out + 4*(size_t)i + 2) = __floats2half2_rn(x.z, x.w);
}

// ---------------------------------------------------------------------------
// strided convert: fp32 (strided rows) -> packed fp16 (for V slice)
// ---------------------------------------------------------------------------
__global__ void convert_strided_kernel(const float* __restrict__ X,
                                       __half* __restrict__ out,
                                       int width, int srcstride, int coloff, int n4)
{
    int i = blockIdx.x * blockDim.x + threadIdx.x;
    if (i >= n4) return;
    int e0 = i * 4;
    int row = e0 / width, col = e0 % width;
    const float* src = X + (size_t)row * srcstride + coloff + col;
    float4 x = *reinterpret_cast<const float4*>(src);
    *reinterpret_cast<__half2*>(out + (size_t)e0) = __floats2half2_rn(x.x, x.y);
    *reinterpret_cast<__half2*>(out + (size_t)e0 + 2) = __floats2half2_rn(x.z, x.w);
}

// ---------------------------------------------------------------------------
// rope + convert to fp16 (+ optional scale), reading fused QKV buffer
// ---------------------------------------------------------------------------
__global__ void rope_f16_kernel(const float* __restrict__ X,
                                const float* __restrict__ cosb,
                                const float* __restrict__ sinb,
                                __half* __restrict__ out,
                                float scale, int nheads,
                                int rowstride, int coloff)
{
    int idx = blockIdx.x * blockDim.x + threadIdx.x;
    int half = idx & 63;
    int hrow = idx >> 6;
    int rowidx = hrow / nheads;
    int head = hrow - rowidx * nheads;
    int s = rowidx % S;
    const float* src = X + (size_t)rowidx * rowstride + coloff + head * HD;
    size_t dbase = (size_t)hrow * HD;
    float x0 = src[half];
    float x1 = src[half + 64];
    float c0 = cosb[s * 64 + (half >> 1)];
    float s0 = sinb[s * 64 + (half >> 1)];
    float c1 = cosb[s * 64 + ((half + 64) >> 1)];
    float s1 = sinb[s * 64 + ((half + 64) >> 1)];
    out[dbase + half]      = __float2half_rn((x0 * c0 - x1 * s0) * scale);
    out[dbase + half + 64] = __float2half_rn((x1 * c1 + x0 * s1) * scale);
}

// ---------------------------------------------------------------------------
// transpose + convert: W [R, C] fp32 -> T [C, R] fp16 (z: up to 2 pairs)
// ---------------------------------------------------------------------------
__global__ void transpose_convert_kernel(const float* __restrict__ W0,
                                         __half* __restrict__ T0,
                                         const float* __restrict__ W1,
                                         __half* __restrict__ T1,
                                         int R, int C)
{
    const float* W = blockIdx.z ? W1 : W0;
    __half* T = blockIdx.z ? T1 : T0;
    __shared__ float t[32][33];
    int c0 = blockIdx.x * 32, r0 = blockIdx.y * 32;
    int tx = threadIdx.x, ty = threadIdx.y;
    #pragma unroll
    for (int i = 0; i < 32; i += 8)
        t[ty + i][tx] = W[(size_t)(r0 + ty + i) * C + c0 + tx];
    __syncthreads();
    #pragma unroll
    for (int i = 0; i < 32; i += 8)
        T[(size_t)(c0 + ty + i) * R + r0 + tx] = __float2half_rn(t[tx][ty + i]);
}

// ---------------------------------------------------------------------------
// fp16 single-pass GEMM: CTA 256x128, 8 warps (4x2), warp tile 64x64, BK=64,
// 2-stage cp.async, ldmatrix fragments. C[M,N] = A[M,K] @ Bm[N,K]^T, fp32 out.
// ---------------------------------------------------------------------------
#define ASTR 72
#define FOFF_B (256*ASTR)
#define FSTG (384*ASTR)            // halfs per stage = 27648
#define GEMMH_SMEM (2*FSTG*2)      // 110592 bytes

__global__ __launch_bounds__(256, 1)
void gemm_f16_kernel(float* __restrict__ C,
    const __half* __restrict__ A, const __half* __restrict__ Bm,
    int M, int N, int K)
{
    extern __shared__ __half smh[];
    const uint32_t smem_base = smem_u32(smh);
    const int tid = threadIdx.x;
    const int wid = tid >> 5, lane = tid & 31;
    const int g = lane >> 2, tig = lane & 3;
    const int wm = wid >> 1, wn = wid & 1;
    const int m0 = blockIdx.y * 256, n0 = blockIdx.x * 128;
    const int nch = K >> 6;

    const int rowselA = ((lane >> 3) & 1) * 8 + (lane & 7);
    const int colselA = ((lane >> 4) & 1) * 8;
    const int bcolsel = ((lane >> 4) & 1) * 8 + (lane & 7);
    const int bksel   = ((lane >> 3) & 1) * 8;

    auto load_chunk = [&](int c, int stage) {
        const int k0 = c << 6;
        const uint32_t sb = smem_base + (uint32_t)(stage * FSTG) * 2;
        #pragma unroll
        for (int i = 0; i < 8; ++i) {
            int v = i * 256 + tid; int r = v >> 3, ch = v & 7;
            cp16(sb + (uint32_t)(r * ASTR + ch * 8) * 2,
                 A + (size_t)(m0 + r) * K + k0 + ch * 8);
        }
        #pragma unroll
        for (int i = 0; i < 4; ++i) {
            int v = i * 256 + tid; int r = v >> 3, ch = v & 7;
            cp16(sb + (uint32_t)(FOFF_B + r * ASTR + ch * 8) * 2,
                 Bm + (size_t)(n0 + r) * K + k0 + ch * 8);
        }
    };

    float acc[4][8][4];
    #pragma unroll
    for (int mi = 0; mi < 4; mi++)
        #pragma unroll
        for (int ni = 0; ni < 8; ni++)
            #pragma unroll
            for (int r = 0; r < 4; r++) acc[mi][ni][r] = 0.f;

    load_chunk(0, 0);
    CP_COMMIT();

    for (int c = 0; c < nch; ++c) {
        if (c + 1 < nch) { load_chunk(c + 1, (c + 1) & 1); CP_COMMIT(); CP_WAIT(1); }
        else             { CP_WAIT(0); }
        __syncthreads();

        const uint32_t stg = smem_base + (uint32_t)((c & 1) * FSTG) * 2;
        const uint32_t bA = stg;
        const uint32_t bB = stg + (uint32_t)FOFF_B * 2;

        #pragma unroll
        for (int ks = 0; ks < 4; ++ks) {
            const int kk0 = ks * 16;
            uint32_t Ah[4][4], Bh[4][4];
            #pragma unroll
            for (int mi = 0; mi < 4; ++mi) {
                uint32_t ar = (uint32_t)((wm * 64 + mi * 16 + rowselA) * ASTR
                                         + kk0 + colselA) * 2;
                ldmx4(Ah[mi], bA + ar);
            }
            #pragma unroll
            for (int nip = 0; nip < 4; ++nip) {
                uint32_t br = (uint32_t)((wn * 64 + nip * 16 + bcolsel) * ASTR
                                         + kk0 + bksel) * 2;
                ldmx4(Bh[nip], bB + br);
            }
            #pragma unroll
            for (int mi = 0; mi < 4; ++mi)
                #pragma unroll
                for (int ni = 0; ni < 8; ++ni)
                    mma16816h(acc[mi][ni], Ah[mi], &Bh[ni >> 1][(ni & 1) * 2]);
        }
        __syncthreads();
    }

    #pragma unroll
    for (int mi = 0; mi < 4; ++mi) {
        int rm = m0 + wm * 64 + mi * 16 + g;
        #pragma unroll
        for (int ni = 0; ni < 8; ++ni) {
            int cn = n0 + wn * 64 + ni * 8 + 2 * tig;
            *(float2*)(C + (size_t)rm * N + cn) =
                make_float2(acc[mi][ni][0], acc[mi][ni][1]);
            *(float2*)(C + (size_t)(rm + 8) * N + cn) =
                make_float2(acc[mi][ni][2], acc[mi][ni][3]);
        }
    }
}

// ---------------------------------------------------------------------------
// All-fp16 FA2 flash attention, 32 q-rows per warp (2x16-row blocks).
// CTA = 256 q-rows, FN=64 keys/tile, 256 threads. K/V fragments reused
// across both row blocks -> LDS:tensor ratio 1.25 (was 2.25).
// smem: Q (69632) + 2 KV stages (34816 each) = 139264 bytes.
// ---------------------------------------------------------------------------
#define QSF 136
#define STG_KV (2*64*QSF*2)           // 34816 bytes per stage (K + V)
#define OFF_KV (256*QSF*2)            // 69632
#define FLASH_SMEM (OFF_KV + 2*STG_KV)   // 139264 bytes

__global__ __launch_bounds__(256, 1) void flash_hmma_kernel(
    const __half* __restrict__ Q16, const __half* __restrict__ K16,
    const __half* __restrict__ V16, __half* __restrict__ O16)
{
    const int m_tile = gridDim.x - 1 - blockIdx.x;   // heavy CTAs first
    const int h = blockIdx.y;
    const int b = blockIdx.z;
    const int kvh = h / GROUPS;
    const int tid = threadIdx.x;
    const int warp = tid >> 5, lane = tid & 31;
    const int g = lane >> 2, tig = lane & 3;
    const int m0 = m_tile * 256;
    const int wrow = warp * 32;

    extern __shared__ char smc[];
    const uint32_t base = smem_u32(smc);

    const int rowselA = ((lane >> 3) & 1) * 8 + (lane & 7);
    const int colselA = ((lane >> 4) & 1) * 8;
    const int bcolsel = ((lane >> 4) & 1) * 8 + (lane & 7);
    const int bksel   = ((lane >> 3) & 1) * 8;
    const uint32_t voff = (uint32_t)(((lane & 7) + ((lane >> 3) & 1) * 8) * QSF
                                     + (lane >> 4) * 8);

    auto load_kv = [&](int nt, int stage) {
        const int n0 = nt * 64;
        const uint32_t sb = base + OFF_KV + (uint32_t)stage * STG_KV;
        #pragma unroll
        for (int i = 0; i < 8; ++i) {
            int v = i * 256 + tid;
            int mat = v >> 10;
            int r = (v >> 4) & 63;
            int ch = v & 15;
            const __half* src = (mat ? V16 : K16)
                + (((size_t)b * S + n0 + r) * KVH + kvh) * HD + ch * 8;
            cp16(sb + (uint32_t)(mat * (64 * QSF) + r * QSF + ch * 8) * 2, src);
        }
    };

    // Q tile: 256 rows x 128 halfs = 4096 16B chunks
    #pragma unroll
    for (int i = 0; i < 16; ++i) {
        int v = i * 256 + tid;
        int r = v >> 4;
        int ch = v & 15;
        const __half* src = Q16 + (((size_t)b * S + m0 + r) * H + h) * HD + ch * 8;
        cp16(base + (uint32_t)(r * QSF + ch * 8) * 2, src);
    }
    load_kv(0, 0);
    CP_COMMIT();

    float acc[2][16][4];
    #pragma unroll
    for (int mi = 0; mi < 2; ++mi)
        #pragma unroll
        for (int ni = 0; ni < 16; ++ni)
            #pragma unroll
            for (int r = 0; r < 4; ++r) acc[mi][ni][r] = 0.f;

    float m_run[2][2] = {{-1e30f, -1e30f}, {-1e30f, -1e30f}};
    float l_run[2][2] = {{0.f, 0.f}, {0.f, 0.f}};

    const int ntmax = 4 * m_tile + 3;
    for (int nt = 0; nt <= ntmax; ++nt) {
        const int n0 = nt * 64;
        if (nt < ntmax) { load_kv(nt + 1, (nt + 1) & 1); CP_COMMIT(); CP_WAIT(1); }
        else            { CP_WAIT(0); }
        __syncthreads();

        const uint32_t kvb = base + OFF_KV + (uint32_t)(nt & 1) * STG_KV;
        const uint32_t bK = kvb;
        const uint32_t bV = kvb + (uint32_t)(64 * QSF) * 2;

        // ---- S = Q @ K^T (both row blocks share K fragments) ----
        float cs[2][8][4];
        #pragma unroll
        for (int mi = 0; mi < 2; ++mi)
            #pragma unroll
            for (int ni = 0; ni < 8; ++ni)
                #pragma unroll
                for (int r = 0; r < 4; ++r) cs[mi][ni][r] = 0.f;

        #pragma unroll
        for (int ks = 0; ks < 8; ++ks) {
            const int kk0 = ks * 16;
            uint32_t qh[2][4];
            #pragma unroll
            for (int mi = 0; mi < 2; ++mi)
                ldmx4(qh[mi], base + (uint32_t)((wrow + mi * 16 + rowselA) * QSF
                                                + kk0 + colselA) * 2);
            #pragma unroll
            for (int nip = 0; nip < 4; ++nip) {
                uint32_t kh[4];
                ldmx4(kh, bK + (uint32_t)((nip * 16 + bcolsel) * QSF + kk0 + bksel) * 2);
                #pragma unroll
                for (int mi = 0; mi < 2; ++mi) {
                    mma16816h(cs[mi][2 * nip],     qh[mi], kh);
                    mma16816h(cs[mi][2 * nip + 1], qh[mi], kh + 2);
                }
            }
        }

        // ---- causal mask + register softmax per row block ----
        #pragma unroll
        for (int mi = 0; mi < 2; ++mi) {
            const int r0g = m0 + wrow + mi * 16 + g;
            const int colb = n0 + 2 * tig;
            #pragma unroll
            for (int ni = 0; ni < 8; ++ni) {
                int c = colb + ni * 8;
                if (c > r0g)         cs[mi][ni][0] = -1e30f;
                if (c + 1 > r0g)     cs[mi][ni][1] = -1e30f;
                if (c > r0g + 8)     cs[mi][ni][2] = -1e30f;
                if (c + 1 > r0g + 8) cs[mi][ni][3] = -1e30f;
            }
            float mx0 = -1e30f, mx1 = -1e30f;
            #pragma unroll
            for (int ni = 0; ni < 8; ++ni) {
                mx0 = fmaxf(mx0, fmaxf(cs[mi][ni][0], cs[mi][ni][1]));
                mx1 = fmaxf(mx1, fmaxf(cs[mi][ni][2], cs[mi][ni][3]));
            }
            mx0 = fmaxf(mx0, __shfl_xor_sync(0xFFFFFFFFu, mx0, 1));
            mx0 = fmaxf(mx0, __shfl_xor_sync(0xFFFFFFFFu, mx0, 2));
            mx1 = fmaxf(mx1, __shfl_xor_sync(0xFFFFFFFFu, mx1, 1));
            mx1 = fmaxf(mx1, __shfl_xor_sync(0xFFFFFFFFu, mx1, 2));
            const float mn0 = fmaxf(m_run[mi][0], mx0);
            const float mn1 = fmaxf(m_run[mi][1], mx1);
            const float corr0 = __expf(m_run[mi][0] - mn0);
            const float corr1 = __expf(m_run[mi][1] - mn1);
            float sum0 = 0.f, sum1 = 0.f;
            #pragma unroll
            for (int ni = 0; ni < 8; ++ni) {
                cs[mi][ni][0] = __expf(cs[mi][ni][0] - mn0); sum0 += cs[mi][ni][0];
                cs[mi][ni][1] = __expf(cs[mi][ni][1] - mn0); sum0 += cs[mi][ni][1];
                cs[mi][ni][2] = __expf(cs[mi][ni][2] - mn1); sum1 += cs[mi][ni][2];
                cs[mi][ni][3] = __expf(cs[mi][ni][3] - mn1); sum1 += cs[mi][ni][3];
            }
            sum0 += __shfl_xor_sync(0xFFFFFFFFu, sum0, 1);
            sum0 += __shfl_xor_sync(0xFFFFFFFFu, sum0, 2);
            sum1 += __shfl_xor_sync(0xFFFFFFFFu, sum1, 1);
            sum1 += __shfl_xor_sync(0xFFFFFFFFu, sum1, 2);
            l_run[mi][0] = l_run[mi][0] * corr0 + sum0;
            l_run[mi][1] = l_run[mi][1] * corr1 + sum1;
            m_run[mi][0] = mn0;
            m_run[mi][1] = mn1;
            #pragma unroll
            for (int ni = 0; ni < 16; ++ni) {
                acc[mi][ni][0] *= corr0; acc[mi][ni][1] *= corr0;
                acc[mi][ni][2] *= corr1; acc[mi][ni][3] *= corr1;
            }
        }

        // ---- O += P @ V (both row blocks share V fragments) ----
        #pragma unroll
        for (int kp = 0; kp < 4; ++kp) {
            uint32_t ap[2][4];
            #pragma unroll
            for (int mi = 0; mi < 2; ++mi)
                #pragma unroll
                for (int t = 0; t < 4; ++t) {
                    int nn = 2 * kp + (t >> 1);
                    int j0 = (t & 1) * 2;
                    __half2 p = __floats2half2_rn(cs[mi][nn][j0], cs[mi][nn][j0 + 1]);
                    ap[mi][t] = *reinterpret_cast<uint32_t*>(&p);
                }
            #pragma unroll
            for (int np = 0; np < 8; ++np) {
                uint32_t bh[4];
                ldmx4t(bh, bV + (uint32_t)(voff + kp * 16 * QSF + np * 16) * 2);
                #pragma unroll
                for (int mi = 0; mi < 2; ++mi) {
                    mma16816h(acc[mi][2 * np],     ap[mi], bh);
                    mma16816h(acc[mi][2 * np + 1], ap[mi], bh + 2);
                }
            }
        }
        __syncthreads();
    }

    #pragma unroll
    for (int mi = 0; mi < 2; ++mi) {
        const float inv0 = 1.f / l_run[mi][0];
        const float inv1 = 1.f / l_run[mi][1];
        const size_t row0 = (size_t)b * S + m0 + wrow + mi * 16 + g;
        __half* o0 = O16 + row0 * (H * HD) + h * HD;
        __half* o1 = o0 + 8 * (size_t)(H * HD);
        #pragma unroll
        for (int ni = 0; ni < 16; ++ni) {
            int c = ni * 8 + 2 * tig;
            *(__half2*)(o0 + c) =
                __floats2half2_rn(acc[mi][ni][0] * inv0, acc[mi][ni][1] * inv0);
            *(__half2*)(o1 + c) =
                __floats2half2_rn(acc[mi][ni][2] * inv1, acc[mi][ni][3] * inv1);
        }
    }
}

// ---------------------------------------------------------------------------
extern "C" void kernel_launch(void* const* d_in, const int* in_sizes, int n_in,
                              void* d_out, int out_size)
{
    const float* x    = (const float*)d_in[0];
    const float* cosb = (const float*)d_in[1];
    const float* sinb = (const float*)d_in[2];
    const float* Wq   = (const float*)d_in[4];
    const float* Wk   = (const float*)d_in[5];
    const float* Wv   = (const float*)d_in[6];
    const float* Wo   = (const float*)d_in[7];
    float* out = (float*)d_out;

    float* QKVp;
    cudaGetSymbolAddress((void**)&QKVp, g_QKV);
    __half *x16, *wqkv16, *wo16, *o16, *q16, *k16, *v16;
    cudaGetSymbolAddress((void**)&x16, g_x16);
    cudaGetSymbolAddress((void**)&wqkv16, g_Wqkv16T);
    cudaGetSymbolAddress((void**)&wo16, g_Wo16T);
    cudaGetSymbolAddress((void**)&o16, g_O16);
    cudaGetSymbolAddress((void**)&q16, g_Q16);
    cudaGetSymbolAddress((void**)&k16, g_K16);
    cudaGetSymbolAddress((void**)&v16, g_V16);

    const int M = M_ROWS;  // 4096

    // prep: convert x to fp16; transpose+convert all weights
    convert_kernel<<<(M * D / 4) / 256, 256>>>(x, x16, M * D / 4);
    transpose_convert_kernel<<<dim3(D / 32, D / 32, 2), dim3(32, 8)>>>(
        Wq, wqkv16, Wo, wo16, D, H * HD);   // both are [2048, 2048]
    transpose_convert_kernel<<<dim3((KVH * HD) / 32, D / 32, 2), dim3(32, 8)>>>(
        Wk, wqkv16 + (size_t)(H * HD) * D,
        Wv, wqkv16 + (size_t)(H * HD + KVH * HD) * D, D, KVH * HD);

    cudaFuncSetAttribute(gemm_f16_kernel,
                         cudaFuncAttributeMaxDynamicSharedMemorySize, GEMMH_SMEM);

    // fused QKV projection: [4096, 3072], fp16 single-pass, fp32 out
    gemm_f16_kernel<<<dim3(NQKV / 128, M / 256), 256, GEMMH_SMEM>>>(
        QKVp, x16, wqkv16, M, NQKV, D);

    // rope + convert to fp16 (Q scaled); V strided convert
    rope_f16_kernel<<<(B * S * H * 64) / 256, 256>>>(
        QKVp, cosb, sinb, q16, SCALE, H, NQKV, 0);
    rope_f16_kernel<<<(B * S * KVH * 64) / 256, 256>>>(
        QKVp, cosb, sinb, k16, 1.0f, KVH, NQKV, H * HD);
    convert_strided_kernel<<<(M * KVH * HD / 4) / 256, 256>>>(
        QKVp, v16, KVH * HD, NQKV, H * HD + KVH * HD, M * KVH * HD / 4);

    // all-fp16 flash attention (256 q-rows/CTA, 32 rows/warp)
    cudaFuncSetAttribute(flash_hmma_kernel,
                         cudaFuncAttributeMaxDynamicSharedMemorySize, FLASH_SMEM);
    flash_hmma_kernel<<<dim3(S / 256, H, B), 256, FLASH_SMEM>>>(
        q16, k16, v16, o16);

    // output projection: fp16 single-pass
    gemm_f16_kernel<<<dim3(D / 128, M / 256), 256, GEMMH_SMEM>>>(
        out, o16, wo16, M, D, D);
}